// round 4
// baseline (speedup 1.0000x reference)
#include <cuda_runtime.h>
#include <math.h>

#define IMG 512
#define BS  32
#define OH  255
#define OW  255

#define TC   32     // cells per tile dim (tile = 64x64 out pixels)
#define NP   33     // patches per tile dim
#define SIMW 34     // sim row stride (even, padded)
#define TR   68     // img halo tile rows/cols (data)
#define TSTR 70     // tile row stride (even, padded; cols 68,69 zeroed)

typedef unsigned long long ull;

// packed (w,w) weights; W2/W3 pre-scaled by 0.5 (relu scale folding)
__constant__ float2 cwts[168];
__device__ float2 g_stage[168];

__global__ void prep_kernel(const float* __restrict__ W1, const float* __restrict__ b1,
                            const float* __restrict__ W2, const float* __restrict__ b2,
                            const float* __restrict__ W3, const float* __restrict__ b3) {
    int t = threadIdx.x;
    if (t >= 168) return;
    float v;
    if (t < 64)       v = W1[t];
    else if (t < 68)  v = b1[t - 64];
    else if (t < 84)  v = 0.5f * W2[t - 68];
    else if (t < 88)  v = b2[t - 84];
    else if (t < 152) v = 0.5f * W3[t - 88];
    else              v = b3[t - 152];
    g_stage[t] = make_float2(v, v);
}

__device__ __forceinline__ ull pk(float lo, float hi) {
    ull r; asm("mov.b64 %0, {%1, %2};" : "=l"(r) : "f"(lo), "f"(hi)); return r;
}
__device__ __forceinline__ void upk(ull v, float& lo, float& hi) {
    asm("mov.b64 {%0, %1}, %2;" : "=f"(lo), "=f"(hi) : "l"(v));
}
__device__ __forceinline__ ull fma2(ull a, ull b, ull c) {
    ull d; asm("fma.rn.f32x2 %0, %1, %2, %3;" : "=l"(d) : "l"(a), "l"(b), "l"(c)); return d;
}
__device__ __forceinline__ ull add2(ull a, ull b) {
    ull d; asm("add.rn.f32x2 %0, %1, %2;" : "=l"(d) : "l"(a), "l"(b)); return d;
}
// scaled relu: x + |x| = 2*relu(x); the 2x is folded into next-layer weights
__device__ __forceinline__ ull relu2s(ull v) {
    return add2(v, v & 0x7FFFFFFF7FFFFFFFULL);
}

__global__ __launch_bounds__(256, 2)
void fused_kernel(const float* __restrict__ img, float* __restrict__ out) {
    __shared__ __align__(16) float tile[TR * TSTR];
    __shared__ __align__(16) float sim[NP * SIMW];

    const int t  = threadIdx.x;
    const int b0 = blockIdx.x * TC;   // cell col origin
    const int a0 = blockIdx.y * TC;   // cell row origin
    const int bt = blockIdx.z;

    // ---- load 68x68 img halo (rows 2a0-2.., cols 2b0-2..), zero-pad OOB + stride pad
    const int gr0 = 2 * a0 - 2;
    const int gc0 = 2 * b0 - 2;
    const float* imgb = img + (size_t)bt * (IMG * IMG);
    for (int i = t; i < TR * TSTR; i += 256) {
        int r = i / TSTR;
        int c = i - r * TSTR;
        int gr = gr0 + r, gc = gc0 + c;
        float v = 0.0f;
        if (c < TR && (unsigned)gr < IMG && (unsigned)gc < IMG)
            v = __ldg(imgb + (size_t)gr * IMG + gc);
        tile[i] = v;
    }
    __syncthreads();

    // ---- patch phase: 33 rows x 17 horizontal pairs = 561 packed units
    const ull* cw = (const ull*)cwts;   // W1:0 b1:64 W2:68 b2:84 W3:88 b3:152
    for (int u = t; u < NP * 17; u += 256) {
        int py  = u / 17;
        int pxp = u - py * 17;          // pair index; patches px = 2pxp, 2pxp+1

        // gather packed x: lane0 = patch at col 4pxp, lane1 = col 4pxp+2
        ull x[16];
        const float* base = tile + (2 * py) * TSTR + 4 * pxp;
#pragma unroll
        for (int r = 0; r < 4; r++) {
            const float2* rp = reinterpret_cast<const float2*>(base + r * TSTR);
            float2 u0 = rp[0], u1 = rp[1], u2 = rp[2];
            x[r * 4 + 0] = pk(u0.x, u1.x);
            x[r * 4 + 1] = pk(u0.y, u1.y);
            x[r * 4 + 2] = pk(u1.x, u2.x);
            x[r * 4 + 3] = pk(u1.y, u2.y);
        }

        // layer 1: 16 -> 4 (scaled relu)
        ull h[4];
#pragma unroll
        for (int j = 0; j < 4; j++) h[j] = cw[64 + j];
#pragma unroll
        for (int i = 0; i < 16; i++)
#pragma unroll
            for (int j = 0; j < 4; j++) h[j] = fma2(x[i], cw[i * 4 + j], h[j]);
#pragma unroll
        for (int j = 0; j < 4; j++) h[j] = relu2s(h[j]);

        // layer 2: 4 -> 4 (weights pre-scaled 0.5)
        ull g[4];
#pragma unroll
        for (int j = 0; j < 4; j++) g[j] = cw[84 + j];
#pragma unroll
        for (int i = 0; i < 4; i++)
#pragma unroll
            for (int j = 0; j < 4; j++) g[j] = fma2(h[i], cw[68 + i * 4 + j], g[j]);
#pragma unroll
        for (int j = 0; j < 4; j++) g[j] = relu2s(g[j]);

        // layer 3: 4 -> 16 (weights pre-scaled 0.5) + cosine accum; ys = 2*y
        ull dot = 0ULL, nx2 = 0ULL, ny2 = 0ULL;
#pragma unroll
        for (int i = 0; i < 16; i++) {
            ull y = cw[152 + i];
#pragma unroll
            for (int j = 0; j < 4; j++) y = fma2(g[j], cw[88 + j * 16 + i], y);
            y = relu2s(y);
            dot = fma2(x[i], y, dot);      // = 2*true_dot
            nx2 = fma2(x[i], x[i], nx2);
            ny2 = fma2(y, y, ny2);         // = 4*true_ny2
        }
        float da, db, xa2, xb2, ya2, yb2;
        upk(dot, da, db); upk(nx2, xa2, xb2); upk(ny2, ya2, yb2);
        // s = 2d * rsqrt(max(nx2,1e-16)) * rsqrt(max(4ny2,4e-16)); factors of 2 cancel
        float sa = da * rsqrtf(fmaxf(xa2, 1e-16f)) * rsqrtf(fmaxf(ya2, 4e-16f));
        float sb = db * rsqrtf(fmaxf(xb2, 1e-16f)) * rsqrtf(fmaxf(yb2, 4e-16f));

        int oy  = a0 - 1 + py;
        int oxa = b0 - 1 + 2 * pxp;
        bool vy = (unsigned)oy < OH;
        if (!(vy && (unsigned)oxa < OW))       sa = 0.0f;
        if (!(vy && (unsigned)(oxa + 1) < OW)) sb = 0.0f;
        *reinterpret_cast<float2*>(sim + py * SIMW + 2 * pxp) = make_float2(sa, sb);
    }
    __syncthreads();

    // ---- fold: each thread handles 2x2 cells -> 4x4 output pixels (float4 rows)
    const int tx = t & 15;
    const int ty = t >> 4;
    float* outb = out + (size_t)bt * (IMG * IMG);
#pragma unroll
    for (int dy = 0; dy < 2; dy++) {
        int ca = 2 * ty + dy;          // local cell row 0..31
        int a  = a0 + ca;              // global cell row 0..255
        int cb = 2 * tx;               // local cell col of left cell
        const float* s0 = sim + ca * SIMW + cb;
        const float* s1 = s0 + SIMW;
        float p00 = s0[0], p01 = s0[1], p02 = s0[2];
        float p10 = s1[0], p11 = s1[1], p12 = s1[2];
        float sumL = (p00 + p01) + (p10 + p11);
        float sumR = (p01 + p02) + (p11 + p12);
        int bL = b0 + cb, bR = bL + 1;
        float invy = (a == 0 || a == 255) ? 1.0f : 0.5f;
        float invL = (bL == 0 || bL == 255) ? 1.0f : 0.5f;
        float invR = (bR == 255) ? 1.0f : 0.5f;
        float vL = sumL * (invy * invL);
        float vR = sumR * (invy * invR);
        float4 v4 = make_float4(vL, vL, vR, vR);
        float* op = outb + (size_t)(2 * a) * IMG + 2 * bL;
        *reinterpret_cast<float4*>(op) = v4;
        *reinterpret_cast<float4*>(op + IMG) = v4;
    }
}

extern "C" void kernel_launch(void* const* d_in, const int* in_sizes, int n_in,
                              void* d_out, int out_size) {
    const float* img = (const float*)d_in[0];
    float* out = (float*)d_out;

    prep_kernel<<<1, 192>>>((const float*)d_in[1], (const float*)d_in[2],
                            (const float*)d_in[3], (const float*)d_in[4],
                            (const float*)d_in[5], (const float*)d_in[6]);
    void* src = nullptr;
    cudaGetSymbolAddress(&src, g_stage);
    cudaMemcpyToSymbolAsync(cwts, src, 168 * sizeof(float2), 0, cudaMemcpyDeviceToDevice);

    dim3 grid(IMG / (2 * TC), IMG / (2 * TC), BS);   // 8 x 8 x 32
    fused_kernel<<<grid, 256>>>(img, out);
}

// round 5
// speedup vs baseline: 1.7803x; 1.7803x over previous
#include <cuda_runtime.h>
#include <math.h>

#define IMG 512
#define BS  32
#define OH  255
#define OW  255
#define TC  16     // cells per block dim (block = 32x32 output pixels)
#define NP  17     // patches per block dim
#define SIMW 18    // padded sim row stride

// scalar weights, constant memory; W2/W3 pre-scaled by 0.5 (relu scale folding)
__constant__ float cw[168];   // W1:0 b1:64 W2:68 b2:84 W3:88 b3:152
__device__ float g_stage[168];

__global__ void prep_kernel(const float* __restrict__ W1, const float* __restrict__ b1,
                            const float* __restrict__ W2, const float* __restrict__ b2,
                            const float* __restrict__ W3, const float* __restrict__ b3) {
    int t = threadIdx.x;
    if (t >= 168) return;
    float v;
    if (t < 64)       v = W1[t];
    else if (t < 68)  v = b1[t - 64];
    else if (t < 84)  v = 0.5f * W2[t - 68];
    else if (t < 88)  v = b2[t - 84];
    else if (t < 152) v = 0.5f * W3[t - 88];
    else              v = b3[t - 152];
    g_stage[t] = v;
}

__global__ __launch_bounds__(256)
void fused_kernel(const float* __restrict__ img, float* __restrict__ out) {
    __shared__ float sim[NP * SIMW];

    const int t  = threadIdx.x;
    const int b0 = blockIdx.x * TC;
    const int a0 = blockIdx.y * TC;
    const int bt = blockIdx.z;
    const float* imgb = img + (size_t)bt * (IMG * IMG);

    // ---- patch phase: 17x17 patches, gather directly from global (L1/L2-cached)
    for (int p = t; p < NP * NP; p += 256) {
        int py = p / NP;
        int px = p - py * NP;
        int oy = a0 - 1 + py;
        int ox = b0 - 1 + px;
        float s = 0.0f;
        if ((unsigned)oy < OH && (unsigned)ox < OW) {
            const float* base = imgb + (size_t)(2 * oy) * IMG + 2 * ox;
            float x[16];
#pragma unroll
            for (int r = 0; r < 4; r++) {
                float2 v0 = __ldg(reinterpret_cast<const float2*>(base + (size_t)r * IMG));
                float2 v1 = __ldg(reinterpret_cast<const float2*>(base + (size_t)r * IMG + 2));
                x[r * 4 + 0] = v0.x; x[r * 4 + 1] = v0.y;
                x[r * 4 + 2] = v1.x; x[r * 4 + 3] = v1.y;
            }

            // layer 1: 16 -> 4; relu as v+|v| (=2*relu, compensated in W2)
            float h[4];
#pragma unroll
            for (int j = 0; j < 4; j++) h[j] = cw[64 + j];
#pragma unroll
            for (int i = 0; i < 16; i++)
#pragma unroll
                for (int j = 0; j < 4; j++) h[j] = fmaf(x[i], cw[i * 4 + j], h[j]);
#pragma unroll
            for (int j = 0; j < 4; j++) h[j] = h[j] + fabsf(h[j]);

            // layer 2: 4 -> 4 (W2 pre-scaled 0.5 -> true pre-activation)
            float g[4];
#pragma unroll
            for (int j = 0; j < 4; j++) g[j] = cw[84 + j];
#pragma unroll
            for (int i = 0; i < 4; i++)
#pragma unroll
                for (int j = 0; j < 4; j++) g[j] = fmaf(h[i], cw[68 + i * 4 + j], g[j]);
#pragma unroll
            for (int j = 0; j < 4; j++) g[j] = g[j] + fabsf(g[j]);

            // layer 3: 4 -> 16 (W3 pre-scaled 0.5) + fused cosine
            float dot = 0.0f, nx2 = 0.0f, ny2 = 0.0f;
#pragma unroll
            for (int i = 0; i < 16; i++) {
                float y = cw[152 + i];
#pragma unroll
                for (int j = 0; j < 4; j++) y = fmaf(g[j], cw[88 + j * 16 + i], y);
                float yr = y + fabsf(y);           // = 2*relu(y)
                dot = fmaf(x[i], yr, dot);          // = 2*true_dot
                nx2 = fmaf(x[i], x[i], nx2);
                ny2 = fmaf(yr, yr, ny2);            // = 4*true_ny2
            }
            // factors of 2 cancel; eps clamps: nx2@1e-16, 4*ny2@4e-16
            s = dot * rsqrtf(fmaxf(nx2, 1e-16f)) * rsqrtf(fmaxf(ny2, 4e-16f));
        }
        sim[py * SIMW + px] = s;   // invalid patches contribute 0
    }
    __syncthreads();

    // ---- fold: thread -> one cell (a,b) -> 2x2 identical output pixels
    const int tx = t & 15;
    const int ty = t >> 4;
    const int a = a0 + ty;
    const int b = b0 + tx;

    const float* s0 = sim + ty * SIMW + tx;   // patch (a-1, b-1)
    float sum = (s0[0] + s0[1]) + (s0[SIMW] + s0[SIMW + 1]);
    float invy = (a == 0 || a == 255) ? 1.0f : 0.5f;
    float invx = (b == 0 || b == 255) ? 1.0f : 0.5f;
    float v = sum * (invy * invx);

    float2 vv = make_float2(v, v);
    float* op = out + (size_t)bt * (IMG * IMG) + (size_t)(2 * a) * IMG + 2 * b;
    *reinterpret_cast<float2*>(op) = vv;
    *reinterpret_cast<float2*>(op + IMG) = vv;
}

extern "C" void kernel_launch(void* const* d_in, const int* in_sizes, int n_in,
                              void* d_out, int out_size) {
    const float* img = (const float*)d_in[0];
    float* out = (float*)d_out;

    prep_kernel<<<1, 192>>>((const float*)d_in[1], (const float*)d_in[2],
                            (const float*)d_in[3], (const float*)d_in[4],
                            (const float*)d_in[5], (const float*)d_in[6]);
    void* src = nullptr;
    cudaGetSymbolAddress(&src, g_stage);
    cudaMemcpyToSymbolAsync(cw, src, 168 * sizeof(float), 0, cudaMemcpyDeviceToDevice);

    dim3 grid(IMG / (2 * TC), IMG / (2 * TC), BS);   // 16 x 16 x 32
    fused_kernel<<<grid, 256>>>(img, out);
}